// round 5
// baseline (speedup 1.0000x reference)
#include <cuda_runtime.h>

#define NG    32
#define NPG   1024
#define FDIM  128
#define EMB   32

// output layout (float32 concat of (xe, edge_index_out, edge_weight))
#define OFF_SRC 1048576
#define OFF_DST 34603008
#define OFF_W   68157440

__device__ __align__(16) float g_centroid[EMB];
__device__ float g_scale;

// ---------------------------------------------------------------------------
// packed f32x2 helpers (FFMA2 path, PTX-only)
// ---------------------------------------------------------------------------
__device__ __forceinline__ void fma2(unsigned long long& d,
                                     unsigned long long a,
                                     unsigned long long b) {
    asm("fma.rn.f32x2 %0, %1, %2, %0;" : "+l"(d) : "l"(a), "l"(b));
}
__device__ __forceinline__ unsigned long long dup2(float a) {
    unsigned long long r;
    asm("mov.b64 %0, {%1, %1};" : "=l"(r) : "f"(a));
    return r;
}
__device__ __forceinline__ void unpack2(float& lo, float& hi, unsigned long long v) {
    asm("mov.b64 {%0, %1}, %2;" : "=f"(lo), "=f"(hi) : "l"(v));
}

// ---------------------------------------------------------------------------
// K1: xe = x @ W  (32768x128 @ 128x32) -> out[0..1048576)
// ---------------------------------------------------------------------------
__global__ void __launch_bounds__(256, 4) k_gemm(const float* __restrict__ x,
                                                 const float* __restrict__ W,
                                                 float* __restrict__ xe) {
    __shared__ __align__(16) float WsT[32][132];   // [col][k]
    __shared__ __align__(16) float xs[32][128];    // [local row][k]

    const int t = threadIdx.x;
    for (int i = t; i < FDIM * EMB; i += 256) {
        int k = i >> 5, c = i & 31;
        WsT[c][k] = W[i];
    }
    const int warp = t >> 5, lane = t & 31;
    const int lr0 = warp * 4;
    #pragma unroll
    for (int rr = 0; rr < 4; rr++) {
        int row = blockIdx.x * 32 + lr0 + rr;
        float4 v = ((const float4*)(x + (size_t)row * FDIM))[lane];
        *(float4*)&xs[lr0 + rr][lane * 4] = v;
    }
    __syncthreads();

    unsigned long long acc[4] = {0ULL, 0ULL, 0ULL, 0ULL};
    const ulonglong2* wv = (const ulonglong2*)&WsT[lane][0];
    #pragma unroll 8
    for (int kq = 0; kq < 32; kq++) {
        ulonglong2 w2 = wv[kq];
        #pragma unroll
        for (int r = 0; r < 4; r++) {
            ulonglong2 x2 = ((const ulonglong2*)&xs[lr0 + r][0])[kq];
            fma2(acc[r], x2.x, w2.x);
            fma2(acc[r], x2.y, w2.y);
        }
    }
    #pragma unroll
    for (int r = 0; r < 4; r++) {
        float lo, hi;
        unpack2(lo, hi, acc[r]);
        int row = blockIdx.x * 32 + lr0 + r;
        xe[row * EMB + lane] = lo + hi;
    }
}

// ---------------------------------------------------------------------------
// K2: centroid = mean(xe[:1024], axis=0); scale = 0.9/max|xe[:1024]-centroid|
// ---------------------------------------------------------------------------
__global__ void __launch_bounds__(1024) k_stats(const float* __restrict__ xe) {
    __shared__ float ps[32][33];
    __shared__ float cent[32];
    __shared__ float wmax[32];
    const int t = threadIdx.x, lane = t & 31, warp = t >> 5;

    float v[32];
    const float4* xr = (const float4*)(xe + t * EMB);
    #pragma unroll
    for (int i = 0; i < 8; i++) {
        float4 q = xr[i];
        v[i * 4 + 0] = q.x; v[i * 4 + 1] = q.y;
        v[i * 4 + 2] = q.z; v[i * 4 + 3] = q.w;
    }

    float mycol = 0.f;
    #pragma unroll
    for (int c = 0; c < 32; c++) {
        float s = v[c];
        #pragma unroll
        for (int off = 16; off > 0; off >>= 1)
            s += __shfl_xor_sync(0xffffffffu, s, off);
        if (c == lane) mycol = s;
    }
    ps[warp][lane] = mycol;
    __syncthreads();
    if (t < 32) {
        float c = 0.f;
        #pragma unroll
        for (int p = 0; p < 32; p++) c += ps[p][t];
        c *= (1.0f / 1024.0f);
        cent[t] = c;
        g_centroid[t] = c;
    }
    __syncthreads();

    float m = 0.f;
    #pragma unroll
    for (int c = 0; c < 32; c++) m = fmaxf(m, fabsf(v[c] - cent[c]));
    #pragma unroll
    for (int off = 16; off > 0; off >>= 1)
        m = fmaxf(m, __shfl_xor_sync(0xffffffffu, m, off));
    if (lane == 0) wmax[warp] = m;
    __syncthreads();
    if (t == 0) {
        float mm = 0.f;
        #pragma unroll
        for (int p = 0; p < 32; p++) mm = fmaxf(mm, wmax[p]);
        g_scale = 0.9f / mm;
    }
}

// ---------------------------------------------------------------------------
// K3 (symmetric): one CTA per unordered 64x64 block pair (bi<=bj) per graph.
// Gram block computed once; mirror block written straight from registers
// (per-thread 4x4 transpose -> float4 column stores, 32B sectors).
// ---------------------------------------------------------------------------
__global__ void __launch_bounds__(256, 4) k_main(const float* __restrict__ tptr,
                                                 const float* __restrict__ thptr,
                                                 float* __restrict__ out) {
    __shared__ __align__(16) float As[32][64];   // 8 KB
    __shared__ __align__(16) float Bs[32][64];   // 8 KB
    __shared__ float sqa[64], sqb[64];

    const int t = threadIdx.x;          // 256
    const int g = blockIdx.y;

    // decode unordered pair (bi <= bj) from blockIdx.x in [0,136)
    int p = blockIdx.x;
    int bi = 0, off = 0;
    while (off + (16 - bi) <= p) { off += 16 - bi; bi++; }
    const int bj = bi + (p - off);
    const bool diag = (bi == bj);

    const float* xe = out;

    // ---- fill: 128 threads normalize one xe row each into a smem column ----
    if (t < 128) {
        const float4* c4 = (const float4*)g_centroid;
        const float scale = g_scale;
        const int local = t & 63;
        const int node = g * NPG + ((t < 64) ? bi : bj) * 64 + local;
        const float4* xr = (const float4*)(xe + (size_t)node * EMB);
        float sq = 0.f;
        #pragma unroll
        for (int i = 0; i < 8; i++) {
            float4 q = __ldg(&xr[i]);
            float4 cv = c4[i];
            float v0 = (q.x - cv.x) * scale;
            float v1 = (q.y - cv.y) * scale;
            float v2 = (q.z - cv.z) * scale;
            float v3 = (q.w - cv.w) * scale;
            sq = fmaf(v0, v0, fmaf(v1, v1, fmaf(v2, v2, fmaf(v3, v3, sq))));
            int k = i * 4;
            if (t < 64) {
                As[k][local] = v0; As[k + 1][local] = v1;
                As[k + 2][local] = v2; As[k + 3][local] = v3;
            } else {
                Bs[k][local] = v0; Bs[k + 1][local] = v1;
                Bs[k + 2][local] = v2; Bs[k + 3][local] = v3;
            }
        }
        if (t < 64) sqa[local] = sq; else sqb[local] = sq;
    }
    __syncthreads();

    const int tx = t & 15, ty = t >> 4;
    const int r0 = ty * 4, c0 = tx * 4;
    const int gb = g * (NPG * NPG);
    const int nodeg = g * NPG;

    float* sp = out + OFF_SRC;
    float* dp = out + OFF_DST;
    float* wp = out + OFF_W;

    // dst vectors for both regions
    float4 d1, d2;
    {
        int c1 = nodeg + bj * 64 + c0;
        int c2 = nodeg + bi * 64 + r0;   // mirror region cols follow r0
        d1.x = (float)(c1 + 0); d1.y = (float)(c1 + 1);
        d1.z = (float)(c1 + 2); d1.w = (float)(c1 + 3);
        d2.x = (float)(c2 + 0); d2.y = (float)(c2 + 1);
        d2.z = (float)(c2 + 2); d2.w = (float)(c2 + 3);
    }

    unsigned long long acc[4][2];
    #pragma unroll
    for (int i = 0; i < 4; i++) { acc[i][0] = 0ULL; acc[i][1] = 0ULL; }

    #pragma unroll
    for (int kc = 0; kc < 4; kc++) {
        // ---- paced src/dst stores ----
        {
            const int i = kc;
            // forward region: row bi*64+r0+i, cols bj*64+c0..c0+3
            int o1 = gb + (bi * 64 + r0 + i) * NPG + bj * 64 + c0;
            float s1 = (float)(nodeg + bi * 64 + r0 + i);
            __stcs((float4*)(sp + o1), make_float4(s1, s1, s1, s1));
            __stcs((float4*)(dp + o1), d1);
            if (!diag) {
                // mirror region: row bj*64+c0+i, cols bi*64+r0..r0+3
                int o2 = gb + (bj * 64 + c0 + i) * NPG + bi * 64 + r0;
                float s2 = (float)(nodeg + bj * 64 + c0 + i);
                __stcs((float4*)(sp + o2), make_float4(s2, s2, s2, s2));
                __stcs((float4*)(dp + o2), d2);
            }
        }
        // ---- 8 k-iterations ----
        #pragma unroll
        for (int kk = 0; kk < 8; kk++) {
            int k = kc * 8 + kk;
            float4 a = *(const float4*)&As[k][r0];
            ulonglong2 b = *(const ulonglong2*)&Bs[k][c0];
            unsigned long long ad0 = dup2(a.x);
            unsigned long long ad1 = dup2(a.y);
            unsigned long long ad2 = dup2(a.z);
            unsigned long long ad3 = dup2(a.w);
            fma2(acc[0][0], ad0, b.x); fma2(acc[0][1], ad0, b.y);
            fma2(acc[1][0], ad1, b.x); fma2(acc[1][1], ad1, b.y);
            fma2(acc[2][0], ad2, b.x); fma2(acc[2][1], ad2, b.y);
            fma2(acc[3][0], ad3, b.x); fma2(acc[3][1], ad3, b.y);
        }
    }

    // ---- epilogue: compute 4x4 weight microtile, write forward + mirror ----
    const float temp = *tptr;
    const float ath = fabsf(*thptr);
    float4 sbv = *(const float4*)&sqb[c0];
    float sb[4] = {sbv.x, sbv.y, sbv.z, sbv.w};
    float sa[4];
    {
        float4 sav = *(const float4*)&sqa[r0];
        sa[0] = sav.x; sa[1] = sav.y; sa[2] = sav.z; sa[3] = sav.w;
    }

    float w16[4][4];   // [i][q] = w(row r0+i, col c0+q)
    #pragma unroll
    for (int i = 0; i < 4; i++) {
        #pragma unroll
        for (int ph = 0; ph < 2; ph++) {
            float g0, g1;
            unpack2(g0, g1, acc[i][ph]);
            float D0 = fmaxf(sa[i] + sb[ph * 2 + 0] - 2.f * g0, 0.f);
            float D1 = fmaxf(sa[i] + sb[ph * 2 + 1] - 2.f * g1, 0.f);
            w16[i][ph * 2 + 0] = __fdividef(1.f, 1.f + __expf(-temp * (ath - D0)));
            w16[i][ph * 2 + 1] = __fdividef(1.f, 1.f + __expf(-temp * (ath - D1)));
        }
    }

    #pragma unroll
    for (int i = 0; i < 4; i++) {
        int o1 = gb + (bi * 64 + r0 + i) * NPG + bj * 64 + c0;
        float4 wv = make_float4(w16[i][0], w16[i][1], w16[i][2], w16[i][3]);
        __stcs((float4*)(wp + o1), wv);
    }
    if (!diag) {
        #pragma unroll
        for (int q = 0; q < 4; q++) {
            int o2 = gb + (bj * 64 + c0 + q) * NPG + bi * 64 + r0;
            float4 mv = make_float4(w16[0][q], w16[1][q], w16[2][q], w16[3][q]);
            __stcs((float4*)(wp + o2), mv);
        }
    }
}

// ---------------------------------------------------------------------------
extern "C" void kernel_launch(void* const* d_in, const int* in_sizes, int n_in,
                              void* d_out, int out_size) {
    const float* x    = (const float*)d_in[0];
    const float* W    = (const float*)d_in[1];
    const float* temp = (const float*)d_in[2];
    const float* thr  = (const float*)d_in[3];
    float* out = (float*)d_out;

    k_gemm <<<1024, 256>>>(x, W, out);
    k_stats<<<1, 1024>>>(out);
    k_main <<<dim3(136, NG), 256>>>(temp, thr, out);
}

// round 7
// speedup vs baseline: 1.3344x; 1.3344x over previous
#include <cuda_runtime.h>

#define NG    32
#define NPG   1024
#define FDIM  128
#define EMB   32

// output layout (float32 concat of (xe, edge_index_out, edge_weight))
#define OFF_SRC 1048576
#define OFF_DST 34603008
#define OFF_W   68157440

__device__ __align__(16) float g_centroid[EMB];
__device__ float g_scale;

// ---------------------------------------------------------------------------
// packed f32x2 helpers (FFMA2 path, PTX-only)
// ---------------------------------------------------------------------------
__device__ __forceinline__ void fma2(unsigned long long& d,
                                     unsigned long long a,
                                     unsigned long long b) {
    asm("fma.rn.f32x2 %0, %1, %2, %0;" : "+l"(d) : "l"(a), "l"(b));
}
__device__ __forceinline__ unsigned long long dup2(float a) {
    unsigned long long r;
    asm("mov.b64 %0, {%1, %1};" : "=l"(r) : "f"(a));
    return r;
}
__device__ __forceinline__ void unpack2(float& lo, float& hi, unsigned long long v) {
    asm("mov.b64 {%0, %1}, %2;" : "=f"(lo), "=f"(hi) : "l"(v));
}

// ---------------------------------------------------------------------------
// K1: xe = x @ W  (32768x128 @ 128x32) -> out[0..1048576)
// 4 independent FFMA2 chains per row to cut exposed latency.
// ---------------------------------------------------------------------------
__global__ void __launch_bounds__(256) k_gemm(const float* __restrict__ x,
                                              const float* __restrict__ W,
                                              float* __restrict__ xe) {
    __shared__ __align__(16) float WsT[32][132];   // [col][k]
    __shared__ __align__(16) float xs[32][128];    // [local row][k]

    const int t = threadIdx.x;
    // W: 128x32 row-major -> WsT[c][k]; float4 loads (4 consecutive c)
    {
        const float4* W4 = (const float4*)W;
        #pragma unroll
        for (int j = 0; j < 4; j++) {
            int p = t + j * 256;           // float4 index 0..1023
            float4 w = W4[p];
            int k = p >> 3;
            int c = (p & 7) * 4;
            WsT[c + 0][k] = w.x; WsT[c + 1][k] = w.y;
            WsT[c + 2][k] = w.z; WsT[c + 3][k] = w.w;
        }
    }
    const int warp = t >> 5, lane = t & 31;
    const int lr0 = warp * 4;
    #pragma unroll
    for (int rr = 0; rr < 4; rr++) {
        int row = blockIdx.x * 32 + lr0 + rr;
        float4 v = ((const float4*)(x + (size_t)row * FDIM))[lane];
        *(float4*)&xs[lr0 + rr][lane * 4] = v;
    }
    __syncthreads();

    // acc[r][h][j]: h = k-half, j = pair component -> 4 chains of depth 16
    unsigned long long acc[4][2][2];
    #pragma unroll
    for (int r = 0; r < 4; r++)
        #pragma unroll
        for (int h = 0; h < 2; h++) { acc[r][h][0] = 0ULL; acc[r][h][1] = 0ULL; }

    const ulonglong2* wv = (const ulonglong2*)&WsT[lane][0];
    #pragma unroll
    for (int kq = 0; kq < 32; kq++) {
        ulonglong2 w2 = wv[kq];
        const int h = kq >> 4;
        #pragma unroll
        for (int r = 0; r < 4; r++) {
            ulonglong2 x2 = ((const ulonglong2*)&xs[lr0 + r][0])[kq];
            fma2(acc[r][h][0], x2.x, w2.x);
            fma2(acc[r][h][1], x2.y, w2.y);
        }
    }
    #pragma unroll
    for (int r = 0; r < 4; r++) {
        float s0, s1, s2, s3, s4, s5, s6, s7;
        unpack2(s0, s1, acc[r][0][0]);
        unpack2(s2, s3, acc[r][0][1]);
        unpack2(s4, s5, acc[r][1][0]);
        unpack2(s6, s7, acc[r][1][1]);
        int row = blockIdx.x * 32 + lr0 + r;
        xe[row * EMB + lane] = ((s0 + s2) + (s1 + s3)) + ((s4 + s6) + (s5 + s7));
    }
}

// ---------------------------------------------------------------------------
// K2: centroid = mean(xe[:1024], axis=0); scale = 0.9/max|xe[:1024]-centroid|
// ---------------------------------------------------------------------------
__global__ void __launch_bounds__(1024) k_stats(const float* __restrict__ xe) {
    __shared__ float ps[32][33];
    __shared__ float cent[32];
    __shared__ float wmax[32];
    const int t = threadIdx.x, lane = t & 31, warp = t >> 5;

    float v[32];
    const float4* xr = (const float4*)(xe + t * EMB);
    #pragma unroll
    for (int i = 0; i < 8; i++) {
        float4 q = xr[i];
        v[i * 4 + 0] = q.x; v[i * 4 + 1] = q.y;
        v[i * 4 + 2] = q.z; v[i * 4 + 3] = q.w;
    }

    float mycol = 0.f;
    #pragma unroll
    for (int c = 0; c < 32; c++) {
        float s = v[c];
        #pragma unroll
        for (int off = 16; off > 0; off >>= 1)
            s += __shfl_xor_sync(0xffffffffu, s, off);
        if (c == lane) mycol = s;
    }
    ps[warp][lane] = mycol;
    __syncthreads();
    if (t < 32) {
        float c = 0.f;
        #pragma unroll
        for (int p = 0; p < 32; p++) c += ps[p][t];
        c *= (1.0f / 1024.0f);
        cent[t] = c;
        g_centroid[t] = c;
    }
    __syncthreads();

    float m = 0.f;
    #pragma unroll
    for (int c = 0; c < 32; c++) m = fmaxf(m, fabsf(v[c] - cent[c]));
    #pragma unroll
    for (int off = 16; off > 0; off >>= 1)
        m = fmaxf(m, __shfl_xor_sync(0xffffffffu, m, off));
    if (lane == 0) wmax[warp] = m;
    __syncthreads();
    if (t == 0) {
        float mm = 0.f;
        #pragma unroll
        for (int p = 0; p < 32; p++) mm = fmaxf(mm, wmax[p]);
        g_scale = 0.9f / mm;
    }
}

// ---------------------------------------------------------------------------
// K3 (symmetric): one CTA per unordered 64x64 block pair (bi<=bj) per graph.
// Mirror block transposed through swizzled smem (As/Bs union) so all global
// stores are row-coalesced STG.128.
// swizzle: float addr = row*64 + (colgrp ^ ((row>>2 & 7)<<2))
// ---------------------------------------------------------------------------
__global__ void __launch_bounds__(256, 4) k_main(const float* __restrict__ tptr,
                                                 const float* __restrict__ thptr,
                                                 float* __restrict__ out) {
    __shared__ __align__(16) float smab[4096];   // As=[0,2048) Bs=[2048,4096); tbuf reuse
    __shared__ float sqa[64], sqb[64];
    #define AS(k, r) smab[(k) * 64 + (r)]
    #define BS(k, c) smab[2048 + (k) * 64 + (c)]

    const int t = threadIdx.x;          // 256
    const int g = blockIdx.y;

    // decode unordered pair (bi <= bj) from blockIdx.x in [0,136)
    int p = blockIdx.x;
    int bi = 0, off = 0;
    while (off + (16 - bi) <= p) { off += 16 - bi; bi++; }
    const int bj = bi + (p - off);
    const bool diag = (bi == bj);

    const float* xe = out;

    // ---- fill: 128 threads normalize one xe row each into a smem column ----
    if (t < 128) {
        const float4* c4 = (const float4*)g_centroid;
        const float scale = g_scale;
        const int local = t & 63;
        const int node = g * NPG + ((t < 64) ? bi : bj) * 64 + local;
        const float4* xr = (const float4*)(xe + (size_t)node * EMB);
        float sq = 0.f;
        #pragma unroll
        for (int i = 0; i < 8; i++) {
            float4 q = __ldg(&xr[i]);
            float4 cv = c4[i];
            float v0 = (q.x - cv.x) * scale;
            float v1 = (q.y - cv.y) * scale;
            float v2 = (q.z - cv.z) * scale;
            float v3 = (q.w - cv.w) * scale;
            sq = fmaf(v0, v0, fmaf(v1, v1, fmaf(v2, v2, fmaf(v3, v3, sq))));
            int k = i * 4;
            if (t < 64) {
                AS(k, local) = v0; AS(k + 1, local) = v1;
                AS(k + 2, local) = v2; AS(k + 3, local) = v3;
            } else {
                BS(k, local) = v0; BS(k + 1, local) = v1;
                BS(k + 2, local) = v2; BS(k + 3, local) = v3;
            }
        }
        if (t < 64) sqa[local] = sq; else sqb[local] = sq;
    }
    __syncthreads();

    const int tx = t & 15, ty = t >> 4;
    const int r0 = ty * 4, c0 = tx * 4;
    const int gb = g * (NPG * NPG);
    const int nodeg = g * NPG;

    float* sp = out + OFF_SRC;
    float* dp = out + OFF_DST;
    float* wp = out + OFF_W;

    // dst vectors: forward cols (bj*64+c0..), mirror cols (bi*64+c0..)
    float4 d1, d2;
    {
        int c1 = nodeg + bj * 64 + c0;
        int c2 = nodeg + bi * 64 + c0;
        d1.x = (float)(c1 + 0); d1.y = (float)(c1 + 1);
        d1.z = (float)(c1 + 2); d1.w = (float)(c1 + 3);
        d2.x = (float)(c2 + 0); d2.y = (float)(c2 + 1);
        d2.z = (float)(c2 + 2); d2.w = (float)(c2 + 3);
    }

    unsigned long long acc[4][2];
    #pragma unroll
    for (int i = 0; i < 4; i++) { acc[i][0] = 0ULL; acc[i][1] = 0ULL; }

    #pragma unroll
    for (int kc = 0; kc < 4; kc++) {
        // ---- paced src/dst stores: both regions row-coalesced ----
        {
            const int i = kc;
            int o1 = gb + (bi * 64 + r0 + i) * NPG + bj * 64 + c0;
            float s1 = (float)(nodeg + bi * 64 + r0 + i);
            __stcs((float4*)(sp + o1), make_float4(s1, s1, s1, s1));
            __stcs((float4*)(dp + o1), d1);
            if (!diag) {
                int o2 = gb + (bj * 64 + r0 + i) * NPG + bi * 64 + c0;
                float s2 = (float)(nodeg + bj * 64 + r0 + i);
                __stcs((float4*)(sp + o2), make_float4(s2, s2, s2, s2));
                __stcs((float4*)(dp + o2), d2);
            }
        }
        // ---- 8 k-iterations ----
        #pragma unroll
        for (int kk = 0; kk < 8; kk++) {
            int k = kc * 8 + kk;
            float4 a = *(const float4*)&AS(k, r0);
            ulonglong2 b = *(const ulonglong2*)&BS(k, c0);
            unsigned long long ad0 = dup2(a.x);
            unsigned long long ad1 = dup2(a.y);
            unsigned long long ad2 = dup2(a.z);
            unsigned long long ad3 = dup2(a.w);
            fma2(acc[0][0], ad0, b.x); fma2(acc[0][1], ad0, b.y);
            fma2(acc[1][0], ad1, b.x); fma2(acc[1][1], ad1, b.y);
            fma2(acc[2][0], ad2, b.x); fma2(acc[2][1], ad2, b.y);
            fma2(acc[3][0], ad3, b.x); fma2(acc[3][1], ad3, b.y);
        }
    }

    // ---- epilogue: weights ----
    const float temp = *tptr;
    const float ath = fabsf(*thptr);
    float4 sbv = *(const float4*)&sqb[c0];
    float sb[4] = {sbv.x, sbv.y, sbv.z, sbv.w};
    float sa[4];
    {
        float4 sav = *(const float4*)&sqa[r0];
        sa[0] = sav.x; sa[1] = sav.y; sa[2] = sav.z; sa[3] = sav.w;
    }

    float w16[4][4];   // [i][q] = w(row r0+i, col c0+q)
    #pragma unroll
    for (int i = 0; i < 4; i++) {
        #pragma unroll
        for (int ph = 0; ph < 2; ph++) {
            float g0, g1;
            unpack2(g0, g1, acc[i][ph]);
            float D0 = fmaxf(sa[i] + sb[ph * 2 + 0] - 2.f * g0, 0.f);
            float D1 = fmaxf(sa[i] + sb[ph * 2 + 1] - 2.f * g1, 0.f);
            w16[i][ph * 2 + 0] = __fdividef(1.f, 1.f + __expf(-temp * (ath - D0)));
            w16[i][ph * 2 + 1] = __fdividef(1.f, 1.f + __expf(-temp * (ath - D1)));
        }
    }

    // forward block: rows bi*64+r0+i, cols bj*64+c0.. (coalesced)
    #pragma unroll
    for (int i = 0; i < 4; i++) {
        int o1 = gb + (bi * 64 + r0 + i) * NPG + bj * 64 + c0;
        __stcs((float4*)(wp + o1),
               make_float4(w16[i][0], w16[i][1], w16[i][2], w16[i][3]));
    }

    if (!diag) {
        // transpose through swizzled smem (reuse smab; everyone is done with
        // As/Bs after the mainloop).
        __syncthreads();
        #pragma unroll
        for (int q = 0; q < 4; q++) {
            int mr = c0 + q;                               // mirror row
            int cg = r0 ^ (((mr >> 2) & 7) << 2);          // swizzled col group
            *(float4*)&smab[mr * 64 + cg] =
                make_float4(w16[0][q], w16[1][q], w16[2][q], w16[3][q]);
        }
        __syncthreads();
        #pragma unroll
        for (int i = 0; i < 4; i++) {
            int mr = r0 + i;
            int cg = c0 ^ (((mr >> 2) & 7) << 2);
            float4 v = *(const float4*)&smab[mr * 64 + cg];
            int o2 = gb + (bj * 64 + mr) * NPG + bi * 64 + c0;
            __stcs((float4*)(wp + o2), v);
        }
    }
    #undef AS
    #undef BS
}

// ---------------------------------------------------------------------------
extern "C" void kernel_launch(void* const* d_in, const int* in_sizes, int n_in,
                              void* d_out, int out_size) {
    const float* x    = (const float*)d_in[0];
    const float* W    = (const float*)d_in[1];
    const float* temp = (const float*)d_in[2];
    const float* thr  = (const float*)d_in[3];
    float* out = (float*)d_out;

    k_gemm <<<1024, 256>>>(x, W, out);
    k_stats<<<1, 1024>>>(out);
    k_main <<<dim3(136, NG), 256>>>(temp, thr, out);
}

// round 9
// speedup vs baseline: 1.3616x; 1.0204x over previous
#include <cuda_runtime.h>

#define NG    32
#define NPG   1024
#define FDIM  128
#define EMB   32

// output layout (float32 concat of (xe, edge_index_out, edge_weight))
#define OFF_SRC 1048576
#define OFF_DST 34603008
#define OFF_W   68157440

__device__ __align__(32) float g_centroid[EMB];
__device__ float g_scale;

// ---------------------------------------------------------------------------
// packed f32x2 + 256-bit memory helpers (Blackwell, PTX-only)
// ---------------------------------------------------------------------------
__device__ __forceinline__ void fma2(unsigned long long& d,
                                     unsigned long long a,
                                     unsigned long long b) {
    asm("fma.rn.f32x2 %0, %1, %2, %0;" : "+l"(d) : "l"(a), "l"(b));
}
__device__ __forceinline__ unsigned long long dup2(float a) {
    unsigned long long r;
    asm("mov.b64 %0, {%1, %1};" : "=l"(r) : "f"(a));
    return r;
}
__device__ __forceinline__ void unpack2(float& lo, float& hi, unsigned long long v) {
    asm("mov.b64 {%0, %1}, %2;" : "=f"(lo), "=f"(hi) : "l"(v));
}
__device__ __forceinline__ void ldg256(float4& a, float4& b, const float* p) {
    asm("ld.global.v8.f32 {%0,%1,%2,%3,%4,%5,%6,%7}, [%8];"
        : "=f"(a.x), "=f"(a.y), "=f"(a.z), "=f"(a.w),
          "=f"(b.x), "=f"(b.y), "=f"(b.z), "=f"(b.w)
        : "l"(p));
}
__device__ __forceinline__ void stg256(float* p, float4 a, float4 b) {
    asm volatile("st.global.cs.v8.f32 [%0], {%1,%2,%3,%4,%5,%6,%7,%8};"
                 :: "l"(p), "f"(a.x), "f"(a.y), "f"(a.z), "f"(a.w),
                    "f"(b.x), "f"(b.y), "f"(b.z), "f"(b.w) : "memory");
}
__device__ __forceinline__ void stg256w(float* p, float4 a, float4 b) {
    asm volatile("st.global.v8.f32 [%0], {%1,%2,%3,%4,%5,%6,%7,%8};"
                 :: "l"(p), "f"(a.x), "f"(a.y), "f"(a.z), "f"(a.w),
                    "f"(b.x), "f"(b.y), "f"(b.z), "f"(b.w) : "memory");
}

// ---------------------------------------------------------------------------
// K1: xe = x @ W  (32768x128 @ 128x32) -> out[0..1048576)
// Row-per-lane: each thread holds its full x row in registers; W read from
// smem broadcast-only (1 wavefront per LDS). 4 col-passes of 8 outputs.
// ---------------------------------------------------------------------------
__global__ void __launch_bounds__(256) k_gemm(const float* __restrict__ x,
                                              const float* __restrict__ W,
                                              float* __restrict__ xe) {
    __shared__ __align__(16) float Ws[FDIM * EMB];   // natural [k][c], 16 KB
    const int t = threadIdx.x;
    {
        const float4* W4 = (const float4*)W;
        float4* S4 = (float4*)Ws;
        #pragma unroll
        for (int j = 0; j < 4; j++) S4[t + j * 256] = W4[t + j * 256];
    }

    const int row = blockIdx.x * 256 + t;
    float xr[FDIM];
    {
        const float* gp = x + (size_t)row * FDIM;
        #pragma unroll
        for (int i = 0; i < 16; i++) {
            float4 a, b;
            ldg256(a, b, gp + i * 8);
            xr[i * 8 + 0] = a.x; xr[i * 8 + 1] = a.y;
            xr[i * 8 + 2] = a.z; xr[i * 8 + 3] = a.w;
            xr[i * 8 + 4] = b.x; xr[i * 8 + 5] = b.y;
            xr[i * 8 + 6] = b.z; xr[i * 8 + 7] = b.w;
        }
    }
    __syncthreads();

    float* orow = xe + (size_t)row * EMB;
    for (int p = 0; p < 4; p++) {                 // cols 8p..8p+7
        unsigned long long a0 = 0ULL, a1 = 0ULL, a2 = 0ULL, a3 = 0ULL;
        const ulonglong2* wb = (const ulonglong2*)(Ws + p * 8);
        #pragma unroll
        for (int k = 0; k < FDIM; k++) {
            unsigned long long xd = dup2(xr[k]);
            // row k of W starts at float offset k*32 => k*8 ulonglong2 units
            ulonglong2 w0 = wb[k * 8];            // W[k][8p..8p+3]
            ulonglong2 w1 = wb[k * 8 + 1];        // W[k][8p+4..8p+7]
            fma2(a0, xd, w0.x); fma2(a1, xd, w0.y);
            fma2(a2, xd, w1.x); fma2(a3, xd, w1.y);
        }
        float4 fa, fb;
        unpack2(fa.x, fa.y, a0); unpack2(fa.z, fa.w, a1);
        unpack2(fb.x, fb.y, a2); unpack2(fb.z, fb.w, a3);
        stg256w(orow + p * 8, fa, fb);            // keep in L2 (re-read soon)
    }
}

// ---------------------------------------------------------------------------
// K2: centroid = mean(xe[:1024], axis=0); scale = 0.9/max|xe[:1024]-centroid|
// ---------------------------------------------------------------------------
__global__ void __launch_bounds__(1024) k_stats(const float* __restrict__ xe) {
    __shared__ float ps[32][33];
    __shared__ float cent[32];
    __shared__ float wmax[32];
    const int t = threadIdx.x, lane = t & 31, warp = t >> 5;

    float v[32];
    const float4* xr = (const float4*)(xe + t * EMB);
    #pragma unroll
    for (int i = 0; i < 8; i++) {
        float4 q = xr[i];
        v[i * 4 + 0] = q.x; v[i * 4 + 1] = q.y;
        v[i * 4 + 2] = q.z; v[i * 4 + 3] = q.w;
    }

    float mycol = 0.f;
    #pragma unroll
    for (int c = 0; c < 32; c++) {
        float s = v[c];
        #pragma unroll
        for (int off = 16; off > 0; off >>= 1)
            s += __shfl_xor_sync(0xffffffffu, s, off);
        if (c == lane) mycol = s;
    }
    ps[warp][lane] = mycol;
    __syncthreads();
    if (t < 32) {
        float c = 0.f;
        #pragma unroll
        for (int p = 0; p < 32; p++) c += ps[p][t];
        c *= (1.0f / 1024.0f);
        cent[t] = c;
        g_centroid[t] = c;
    }
    __syncthreads();

    float m = 0.f;
    #pragma unroll
    for (int c = 0; c < 32; c++) m = fmaxf(m, fabsf(v[c] - cent[c]));
    #pragma unroll
    for (int off = 16; off > 0; off >>= 1)
        m = fmaxf(m, __shfl_xor_sync(0xffffffffu, m, off));
    if (lane == 0) wmax[warp] = m;
    __syncthreads();
    if (t == 0) {
        float mm = 0.f;
        #pragma unroll
        for (int p = 0; p < 32; p++) mm = fmaxf(mm, wmax[p]);
        g_scale = 0.9f / mm;
    }
}

// ---------------------------------------------------------------------------
// K3 (symmetric): one CTA per unordered 64x64 block pair (bi<=bj) per graph.
// Fill: 256 threads, half-row each (sq via shfl pair). Mainloop: f32x2 FMA.
// src/dst: 16-col-per-thread layout, STG.256, paced one stream per k-chunk.
// Mirror weights via XOR-swizzled smem transpose (all 16B aligned).
// ---------------------------------------------------------------------------
__global__ void __launch_bounds__(256, 4) k_main(const float* __restrict__ tptr,
                                                 const float* __restrict__ thptr,
                                                 float* __restrict__ out) {
    __shared__ __align__(16) float smab[4096];   // As=[0,2048) Bs=[2048,4096)
    __shared__ float sqa[64], sqb[64];
    #define AS(k, r) smab[(k) * 64 + (r)]
    #define BS(k, c) smab[2048 + (k) * 64 + (c)]

    const int t = threadIdx.x;          // 256
    const int g = blockIdx.y;

    // decode unordered pair (bi <= bj) from blockIdx.x in [0,136)
    int p = blockIdx.x;
    int bi = 0, off = 0;
    while (off + (16 - bi) <= p) { off += 16 - bi; bi++; }
    const int bj = bi + (p - off);
    const bool diag = (bi == bj);

    const float* xe = out;

    // ---- fill: 256 threads, each normalizes HALF an xe row (16 feats) ----
    {
        const int idx = t >> 1;          // 0..127 (row slot)
        const int h = t & 1;             // half selector
        const int local = idx & 63;
        const int node = g * NPG + ((idx < 64) ? bi : bj) * 64 + local;
        const float scale = g_scale;
        const float* xp = xe + (size_t)node * EMB + h * 16;
        const float* cp = g_centroid + h * 16;
        float4 qa, qb, qc, qd, ca, cbv, cc, cd;
        ldg256(qa, qb, xp);
        ldg256(qc, qd, xp + 8);
        ldg256(ca, cbv, cp);
        ldg256(cc, cd, cp + 8);
        float v[16];
        v[0]  = (qa.x - ca.x) * scale;  v[1]  = (qa.y - ca.y) * scale;
        v[2]  = (qa.z - ca.z) * scale;  v[3]  = (qa.w - ca.w) * scale;
        v[4]  = (qb.x - cbv.x) * scale; v[5]  = (qb.y - cbv.y) * scale;
        v[6]  = (qb.z - cbv.z) * scale; v[7]  = (qb.w - cbv.w) * scale;
        v[8]  = (qc.x - cc.x) * scale;  v[9]  = (qc.y - cc.y) * scale;
        v[10] = (qc.z - cc.z) * scale;  v[11] = (qc.w - cc.w) * scale;
        v[12] = (qd.x - cd.x) * scale;  v[13] = (qd.y - cd.y) * scale;
        v[14] = (qd.z - cd.z) * scale;  v[15] = (qd.w - cd.w) * scale;
        float sq = 0.f;
        #pragma unroll
        for (int f = 0; f < 16; f++) {
            sq = fmaf(v[f], v[f], sq);
            int k = h * 16 + f;
            if (idx < 64) AS(k, local) = v[f];
            else          BS(k, local) = v[f];
        }
        sq += __shfl_xor_sync(0xffffffffu, sq, 1);
        if (h == 0) {
            if (idx < 64) sqa[local] = sq; else sqb[local] = sq;
        }
    }
    __syncthreads();

    const int tx = t & 15, ty = t >> 4;
    const int r0 = ty * 4, c0 = tx * 4;
    const int gb = g * (NPG * NPG);
    const int nodeg = g * NPG;

    float* sp = out + OFF_SRC;
    float* dp = out + OFF_DST;
    float* wp = out + OFF_W;

    // paced-store layout: each thread owns 16 consecutive cols of one row
    const int prow = t >> 2;             // 0..63
    const int pc = (t & 3) << 4;         // 0,16,32,48
    const int R1 = bi * 64 + prow;
    const int R2 = bj * 64 + prow;
    const int o1 = gb + R1 * NPG + bj * 64 + pc;
    const int o2 = gb + R2 * NPG + bi * 64 + pc;

    unsigned long long acc[4][2];
    #pragma unroll
    for (int i = 0; i < 4; i++) { acc[i][0] = 0ULL; acc[i][1] = 0ULL; }

    #pragma unroll
    for (int kc = 0; kc < 4; kc++) {
        // ---- paced src/dst: one stream per k-chunk, STG.256 ----
        if (kc == 0) {
            float s = (float)(nodeg + R1);
            float4 sv = make_float4(s, s, s, s);
            stg256(sp + o1, sv, sv);
            stg256(sp + o1 + 8, sv, sv);
        } else if (kc == 1) {
            float c = (float)(nodeg + bj * 64 + pc);
            float4 da = make_float4(c, c + 1.f, c + 2.f, c + 3.f);
            float4 db = make_float4(c + 4.f, c + 5.f, c + 6.f, c + 7.f);
            float4 dc = make_float4(c + 8.f, c + 9.f, c + 10.f, c + 11.f);
            float4 dd = make_float4(c + 12.f, c + 13.f, c + 14.f, c + 15.f);
            stg256(dp + o1, da, db);
            stg256(dp + o1 + 8, dc, dd);
        } else if (kc == 2) {
            if (!diag) {
                float s = (float)(nodeg + R2);
                float4 sv = make_float4(s, s, s, s);
                stg256(sp + o2, sv, sv);
                stg256(sp + o2 + 8, sv, sv);
            }
        } else {
            if (!diag) {
                float c = (float)(nodeg + bi * 64 + pc);
                float4 da = make_float4(c, c + 1.f, c + 2.f, c + 3.f);
                float4 db = make_float4(c + 4.f, c + 5.f, c + 6.f, c + 7.f);
                float4 dc = make_float4(c + 8.f, c + 9.f, c + 10.f, c + 11.f);
                float4 dd = make_float4(c + 12.f, c + 13.f, c + 14.f, c + 15.f);
                stg256(dp + o2, da, db);
                stg256(dp + o2 + 8, dc, dd);
            }
        }
        // ---- 8 k-iterations ----
        #pragma unroll
        for (int kk = 0; kk < 8; kk++) {
            int k = kc * 8 + kk;
            float4 a = *(const float4*)&AS(k, r0);
            ulonglong2 b = *(const ulonglong2*)&BS(k, c0);
            unsigned long long ad0 = dup2(a.x);
            unsigned long long ad1 = dup2(a.y);
            unsigned long long ad2 = dup2(a.z);
            unsigned long long ad3 = dup2(a.w);
            fma2(acc[0][0], ad0, b.x); fma2(acc[0][1], ad0, b.y);
            fma2(acc[1][0], ad1, b.x); fma2(acc[1][1], ad1, b.y);
            fma2(acc[2][0], ad2, b.x); fma2(acc[2][1], ad2, b.y);
            fma2(acc[3][0], ad3, b.x); fma2(acc[3][1], ad3, b.y);
        }
    }

    // ---- epilogue: weights ----
    const float temp = *tptr;
    const float ath = fabsf(*thptr);
    float4 sbv = *(const float4*)&sqb[c0];
    float sb[4] = {sbv.x, sbv.y, sbv.z, sbv.w};
    float sa[4];
    {
        float4 sav = *(const float4*)&sqa[r0];
        sa[0] = sav.x; sa[1] = sav.y; sa[2] = sav.z; sa[3] = sav.w;
    }

    float w16[4][4];   // [i][q] = w(row r0+i, col c0+q)
    #pragma unroll
    for (int i = 0; i < 4; i++) {
        #pragma unroll
        for (int ph = 0; ph < 2; ph++) {
            float g0, g1;
            unpack2(g0, g1, acc[i][ph]);
            float D0 = fmaxf(sa[i] + sb[ph * 2 + 0] - 2.f * g0, 0.f);
            float D1 = fmaxf(sa[i] + sb[ph * 2 + 1] - 2.f * g1, 0.f);
            w16[i][ph * 2 + 0] = __fdividef(1.f, 1.f + __expf(-temp * (ath - D0)));
            w16[i][ph * 2 + 1] = __fdividef(1.f, 1.f + __expf(-temp * (ath - D1)));
        }
    }

    // forward block: rows bi*64+r0+i, cols bj*64+c0.. (coalesced)
    #pragma unroll
    for (int i = 0; i < 4; i++) {
        int o = gb + (bi * 64 + r0 + i) * NPG + bj * 64 + c0;
        __stcs((float4*)(wp + o),
               make_float4(w16[i][0], w16[i][1], w16[i][2], w16[i][3]));
    }

    if (!diag) {
        // transpose through swizzled smem (reuse smab; As/Bs dead now)
        __syncthreads();
        #pragma unroll
        for (int q = 0; q < 4; q++) {
            int mr = c0 + q;                               // mirror row
            int cg = r0 ^ (((mr >> 2) & 7) << 2);          // swizzled col group
            *(float4*)&smab[mr * 64 + cg] =
                make_float4(w16[0][q], w16[1][q], w16[2][q], w16[3][q]);
        }
        __syncthreads();
        #pragma unroll
        for (int i = 0; i < 4; i++) {
            int mr = r0 + i;
            int cg = c0 ^ (((mr >> 2) & 7) << 2);
            float4 v = *(const float4*)&smab[mr * 64 + cg];
            int o = gb + (bj * 64 + mr) * NPG + bi * 64 + c0;
            __stcs((float4*)(wp + o), v);
        }
    }
    #undef AS
    #undef BS
}

// ---------------------------------------------------------------------------
extern "C" void kernel_launch(void* const* d_in, const int* in_sizes, int n_in,
                              void* d_out, int out_size) {
    const float* x    = (const float*)d_in[0];
    const float* W    = (const float*)d_in[1];
    const float* temp = (const float*)d_in[2];
    const float* thr  = (const float*)d_in[3];
    float* out = (float*)d_out;

    k_gemm <<<128, 256>>>(x, W, out);
    k_stats<<<1, 1024>>>(out);
    k_main <<<dim3(136, NG), 256>>>(temp, thr, out);
}